// round 10
// baseline (speedup 1.0000x reference)
#include <cuda_runtime.h>
#include <cuda_bf16.h>

#define H     2048
#define G4    8192          // 4*H gate rows
#define V     28
#define T     512
#define NCTA  148
#define CPB   14            // h-indices per CTA
#define ROWS  56            // gate rows per CTA
#define SMEM_ROWS 49        // rows resident in SMEM; rest (7) stream from L2
#define WMAT  16777216      // G4*H elements per matrix
#define KMAGIC 8421376.0f   // 2^23 + 32768 (biased-u16 float offset)

// dynamic smem layout (u32 units)
#define OFF_W     0
#define OFF_H     (SMEM_ROWS * 1024)            // 50176
#define OFF_PART  (OFF_H + 2048)                // 52224  : 56 rows x 4 slices
#define OFF_C     (OFF_PART + ROWS * 4)         // 52448
#define SMEM_U32  (OFF_C + CPB)                 // 52462
#define SMEM_BYTES (SMEM_U32 * 4)

// ---- device scratch (no allocations allowed) ----
__device__ float          g_table[2u * V * G4]; // [enc/dec][vocab][4H] gate table
__device__ unsigned short g_Wq[2][WMAT];        // biased-u16 quantized Whh
__device__ float          g_wscale[2][G4];      // per-row dequant scales
__device__ float          g_h[2][H];            // double-buffered hidden state
// per-CTA barrier stamps, each on its OWN 128B line (32 u32 stride)
__device__ volatile unsigned g_arr[NCTA * 32];

__device__ __forceinline__ float warpsum(float v) {
#pragma unroll
    for (int o = 16; o; o >>= 1) v += __shfl_xor_sync(0xffffffffu, v, o);
    return v;
}
__device__ __forceinline__ float sigm(float x) { return 1.0f / (1.0f + expf(-x)); }

// All-to-all flag barrier with PADDED slots (one 128B line per CTA).
// Arrival: 148 parallel stores (no atomics). Detection: warp 0 of every CTA
// polls all 148 slots (5 per lane) and votes. Stamps are monotonic and
// persist across graph replays (launch base re-read from own slot).
__device__ __forceinline__ void gbar(unsigned stamp, int lane) {
    __syncthreads();                      // all CTA work program-complete
    if (threadIdx.x == 0) {
        __threadfence();                  // release (cumulative via bar.sync)
        g_arr[blockIdx.x * 32] = stamp;
    }
    if (threadIdx.x < 32) {
        bool ok;
        do {
            unsigned good = 1u;
#pragma unroll
            for (int i = 0; i < 5; i++) {
                const int idx = lane + i * 32;
                if (idx < NCTA)
                    good &= (unsigned)((int)(g_arr[idx * 32] - stamp) >= 0);
            }
            ok = __all_sync(0xffffffffu, good != 0);
        } while (!ok);
        __threadfence();                  // acquire
    }
    __syncthreads();
}

// biased-u16 pair -> 2 fp32 (value = 2^23 + biased) via PRMT; no I2F.
#define CVT_LO(u) __uint_as_float(__byte_perm((u), 0x4B000000u, 0x7410))
#define CVT_HI(u) __uint_as_float(__byte_perm((u), 0x4B000000u, 0x7432))

// ---------------------------------------------------------------------------
// Quantize Whh rows to biased uint16 with per-row fp32 scale.
// ---------------------------------------------------------------------------
__global__ __launch_bounds__(256) void k_quant(
    const float* __restrict__ encW, const float* __restrict__ decW)
{
    __shared__ float s_max[8];
    const int r     = blockIdx.x;       // 0..16383
    const int which = r >> 13;
    const int row   = r & (G4 - 1);
    const int tid = threadIdx.x, lane = tid & 31, w = tid >> 5;

    const float4* W4 = reinterpret_cast<const float4*>(
        (which ? decW : encW) + (size_t)row * H);

    float4 v0 = __ldg(&W4[tid]);
    float4 v1 = __ldg(&W4[tid + 256]);

    float m = fmaxf(fmaxf(fabsf(v0.x), fabsf(v0.y)), fmaxf(fabsf(v0.z), fabsf(v0.w)));
    m = fmaxf(m, fmaxf(fmaxf(fabsf(v1.x), fabsf(v1.y)), fmaxf(fabsf(v1.z), fabsf(v1.w))));
#pragma unroll
    for (int o = 16; o; o >>= 1) m = fmaxf(m, __shfl_xor_sync(0xffffffffu, m, o));
    if (lane == 0) s_max[w] = m;
    __syncthreads();
    if (tid == 0) {
        float mm = s_max[0];
#pragma unroll
        for (int i = 1; i < 8; i++) mm = fmaxf(mm, s_max[i]);
        s_max[0] = mm;
        g_wscale[which][row] = mm * (1.0f / 32766.0f);
    }
    __syncthreads();
    const float mv  = s_max[0];
    const float inv = (mv > 0.0f) ? (32766.0f / mv) : 0.0f;

    ushort4* Q4 = reinterpret_cast<ushort4*>(&g_Wq[which][(size_t)row * H]);
    ushort4 q;
    q.x = (unsigned short)(__float2int_rn(v0.x * inv) + 32768);
    q.y = (unsigned short)(__float2int_rn(v0.y * inv) + 32768);
    q.z = (unsigned short)(__float2int_rn(v0.z * inv) + 32768);
    q.w = (unsigned short)(__float2int_rn(v0.w * inv) + 32768);
    Q4[tid] = q;
    q.x = (unsigned short)(__float2int_rn(v1.x * inv) + 32768);
    q.y = (unsigned short)(__float2int_rn(v1.y * inv) + 32768);
    q.z = (unsigned short)(__float2int_rn(v1.z * inv) + 32768);
    q.w = (unsigned short)(__float2int_rn(v1.w * inv) + 32768);
    Q4[tid + 256] = q;
}

// ---------------------------------------------------------------------------
// Precompute per-vocab gate tables; block 0 also zeroes g_h[0].
// ---------------------------------------------------------------------------
__global__ __launch_bounds__(256) void k_pre(
    const float* __restrict__ enc_emb, const float* __restrict__ enc_Wih,
    const float* __restrict__ enc_bih, const float* __restrict__ enc_bhh,
    const float* __restrict__ dec_emb, const float* __restrict__ dec_Wih,
    const float* __restrict__ dec_bih, const float* __restrict__ dec_bhh)
{
    __shared__ __align__(16) float s_emb[V][256];
    const int tid = threadIdx.x, lane = tid & 31, warp = tid >> 5;

    if (blockIdx.x == 0) {
        for (int j = tid; j < H; j += 256) g_h[0][j] = 0.0f;
    }

    const int   which = (blockIdx.x >= 1024) ? 1 : 0;
    const float* emb = which ? dec_emb : enc_emb;
    const float* Wih = which ? dec_Wih : enc_Wih;
    const float* bih = which ? dec_bih : enc_bih;
    const float* bhh = which ? dec_bhh : enc_bhh;
    const int row = (blockIdx.x & 1023) * 8 + warp;   // 0..8191

    float acc[V];
#pragma unroll
    for (int v = 0; v < V; v++) acc[v] = 0.0f;

    for (int kt = 0; kt < 8; kt++) {
        const int k0 = kt * 256;
        __syncthreads();
        for (int idx = tid; idx < V * 256; idx += 256) {
            int v = idx >> 8, kk = idx & 255;
            s_emb[v][kk] = __ldg(&emb[v * H + k0 + kk]);
        }
        __syncthreads();
        const float4* Wr = reinterpret_cast<const float4*>(Wih + (size_t)row * H + k0);
#pragma unroll
        for (int it = 0; it < 2; it++) {
            const int kl = it * 32 + lane;
            float4 w4 = __ldg(&Wr[kl]);
#pragma unroll
            for (int v = 0; v < V; v++) {
                float4 e = reinterpret_cast<const float4*>(s_emb[v])[kl];
                acc[v] += w4.x * e.x + w4.y * e.y + w4.z * e.z + w4.w * e.w;
            }
        }
    }

    float bias = 0.0f;
#pragma unroll
    for (int v = 0; v < V; v++) {
        float s = warpsum(acc[v]);
        if (lane == 0) {
            if (v == 0) bias = __ldg(&bih[row]) + __ldg(&bhh[row]);
            g_table[(size_t)which * V * G4 + (size_t)v * G4 + row] = s + bias;
        }
    }
}

// ---------------------------------------------------------------------------
// Persistent LSTM kernel. 148 CTAs x 1024 threads. Identical to round 9
// except grid_sync -> gbar (padded-slot store/poll barrier, no atomics).
// ---------------------------------------------------------------------------
__global__ __launch_bounds__(1024, 1) void k_main(
    const int*   __restrict__ x,      const int*   __restrict__ target,
    const float* __restrict__ eps,
    const float* __restrict__ mu_W,    const float* __restrict__ mu_b,
    const float* __restrict__ lv_W,    const float* __restrict__ lv_b,
    float* __restrict__ out)
{
    extern __shared__ __align__(16) unsigned s_dyn[];
    unsigned* s_w     = s_dyn + OFF_W;               // [49][1024] u32 (2 u16)
    float*    s_h     = (float*)(s_dyn + OFF_H);     // [2048]
    float*    s_part  = (float*)(s_dyn + OFF_PART);  // [56][4]
    float*    s_c     = (float*)(s_dyn + OFF_C);     // [14]

    const int tid = threadIdx.x, lane = tid & 31, w = tid >> 5;
    const int g = w >> 2;        // row-group 0..7
    const int q = w & 3;         // k-slice 0..3
    const int j0 = blockIdx.x * CPB;
    int nloc = H - j0;
    if (nloc > CPB) nloc = CPB;
    if (nloc < 0)  nloc = 0;
    const int nrows = nloc * 4;

    if (tid < CPB) s_c[tid] = 0.0f;

    unsigned stamp = g_arr[blockIdx.x * 32];  // launch base (graph-replay safe)
    int rb = 0;

    for (int phase = 0; phase < 2; phase++) {
        const unsigned short* Wq = g_Wq[phase];
        const float* wsc   = g_wscale[phase];
        const float* table = g_table + (size_t)phase * V * G4;

        // ---- load the 49 SMEM-resident weight rows for this phase ----
        __syncthreads();
        {
            const unsigned* Wq32 = reinterpret_cast<const unsigned*>(Wq);
            for (int sidx = 0; sidx < 49; sidx++) {
                int lr = (sidx < 48) ? ((sidx / 6) + 8 * (sidx % 6)) : 48;
                if (lr < nrows) {
                    const int row = (lr & 3) * H + j0 + (lr >> 2);
                    s_w[sidx * 1024 + tid] = __ldg(&Wq32[(size_t)row * 1024 + tid]);
                }
            }
        }
        __syncthreads();

        for (int t = 0; t < T; t++) {
            // prefetch streamed row (one per group, g>=1)
            const int lrs = 48 + g;
            const bool do_stream = (g >= 1) && (lrs < nrows);
            uint2 pf[4];
            if (do_stream) {
                const int row = (lrs & 3) * H + j0 + (lrs >> 2);
                const uint2* gw = reinterpret_cast<const uint2*>(
                    Wq + (size_t)row * H) + q * 128 + lane;
#pragma unroll
                for (int c = 0; c < 4; c++) pf[c] = __ldg(&gw[c * 32]);
            }

            // broadcast full h into smem: one float2 per thread
            {
                float2 hv2 = __ldcg(&reinterpret_cast<const float2*>(g_h[rb])[tid]);
                reinterpret_cast<float2*>(s_h)[tid] = hv2;
            }
            __syncthreads();

            // per-warp h-slice in registers: k = q*512 + c*128 + lane*4
            const float4* sh4 = reinterpret_cast<const float4*>(s_h);
            float4 hv[4];
            float hsum = 0.0f;
#pragma unroll
            for (int c = 0; c < 4; c++) {
                hv[c] = sh4[q * 128 + c * 32 + lane];
                hsum += (hv[c].x + hv[c].y) + (hv[c].z + hv[c].w);
            }

            // SMEM rows: k = 0..5 (all g), plus k=6 for g==0
            const int kmax = (g == 0) ? 7 : 6;
#pragma unroll
            for (int k = 0; k < 7; k++) {
                if (k >= kmax) break;
                const int lr = g + 8 * k;
                if (lr < nrows) {
                    const int sidx = (k < 6) ? (g * 6 + k) : 48;
                    const uint2* wp = reinterpret_cast<const uint2*>(s_w) +
                                      (size_t)sidx * 512 + q * 128 + lane;
                    float acc = 0.0f;
#pragma unroll
                    for (int c = 0; c < 4; c++) {
                        uint2 ab = wp[c * 32];
                        acc = fmaf(CVT_LO(ab.x), hv[c].x, acc);
                        acc = fmaf(CVT_HI(ab.x), hv[c].y, acc);
                        acc = fmaf(CVT_LO(ab.y), hv[c].z, acc);
                        acc = fmaf(CVT_HI(ab.y), hv[c].w, acc);
                    }
                    acc = fmaf(-KMAGIC, hsum, acc);   // remove bias term
                    acc = warpsum(acc);
                    if (lane == 0) s_part[lr * 4 + q] = acc;
                }
            }
            if (do_stream) {
                float acc = 0.0f;
#pragma unroll
                for (int c = 0; c < 4; c++) {
                    acc = fmaf(CVT_LO(pf[c].x), hv[c].x, acc);
                    acc = fmaf(CVT_HI(pf[c].x), hv[c].y, acc);
                    acc = fmaf(CVT_LO(pf[c].y), hv[c].z, acc);
                    acc = fmaf(CVT_HI(pf[c].y), hv[c].w, acc);
                }
                acc = fmaf(-KMAGIC, hsum, acc);
                acc = warpsum(acc);
                if (lane == 0) s_part[lrs * 4 + q] = acc;
            }
            __syncthreads();

            // fused combine + dequant + table + cell update (owner threads)
            if (tid < nloc) {
                const int tok = (phase == 0) ? __ldg(&x[t])
                                             : (t == 0 ? 0 : __ldg(&target[t - 1]));
                float gate[4];
#pragma unroll
                for (int ga = 0; ga < 4; ga++) {
                    const int lr = tid * 4 + ga;
                    const int row = ga * H + j0 + tid;
                    float s = (s_part[lr * 4 + 0] + s_part[lr * 4 + 1]) +
                              (s_part[lr * 4 + 2] + s_part[lr * 4 + 3]);
                    gate[ga] = s * __ldg(&wsc[row]) +
                               __ldg(&table[(size_t)tok * G4 + row]);
                }
                float c = sigm(gate[1]) * s_c[tid] + sigm(gate[0]) * tanhf(gate[2]);
                s_c[tid] = c;
                float h = sigm(gate[3]) * tanhf(c);
                __stcg(&g_h[rb ^ 1][j0 + tid], h);
                if (phase)
                    out[512 + (size_t)t * H + j0 + tid] = h;
            }
            stamp++;
            gbar(stamp, lane);
            rb ^= 1;
        }

        if (phase == 0) {
            // VAE heads: mu, logvar from h_enc (in g_h[rb]); z -> g_h[rb^1]
            {
                float2 hv2 = __ldcg(&reinterpret_cast<const float2*>(g_h[rb])[tid]);
                reinterpret_cast<float2*>(s_h)[tid] = hv2;
            }
            __syncthreads();
            const float4* sh4 = reinterpret_cast<const float4*>(s_h);
            if (w < nloc * 2) {
                const int l = w >> 1, m = w & 1;
                const float* Wm = m ? lv_W : mu_W;
                const int row = j0 + l;
                const float4* W4 = reinterpret_cast<const float4*>(Wm) +
                                   (size_t)row * (H / 4);
                float s = 0.0f;
#pragma unroll 8
                for (int i = lane; i < H / 4; i += 32) {
                    float4 a = __ldg(&W4[i]);
                    float4 b = sh4[i];
                    s += a.x * b.x + a.y * b.y + a.z * b.z + a.w * b.w;
                }
                s = warpsum(s);
                if (lane == 0)
                    s_part[w] = s + __ldg(&(m ? lv_b : mu_b)[row]);
            }
            __syncthreads();
            if (tid < nloc) {
                const int j = j0 + tid;
                const float mu = s_part[tid * 2 + 0];
                const float lv = s_part[tid * 2 + 1];
                out[512 + (size_t)T * H + j]     = mu;
                out[512 + (size_t)T * H + H + j] = lv;
                float z = mu + __ldg(&eps[j]) * expf(0.5f * lv);
                __stcg(&g_h[rb ^ 1][j], z);
            }
            stamp++;
            gbar(stamp, lane);
            rb ^= 1;
        }
    }
}

// ---------------------------------------------------------------------------
// Argmax over hidden dim of each decoder output row (first-index tie-break).
// ---------------------------------------------------------------------------
__global__ __launch_bounds__(256) void k_argmax(float* __restrict__ out)
{
    __shared__ float sv[256];
    __shared__ int   si[256];
    const int t = blockIdx.x;
    const float* row = out + 512 + (size_t)t * H;
    float best = -3.402823466e+38f;
    int   bi = 0;
    for (int j = threadIdx.x; j < H; j += 256) {
        float v = row[j];
        if (v > best) { best = v; bi = j; }
    }
    sv[threadIdx.x] = best;
    si[threadIdx.x] = bi;
    __syncthreads();
    for (int s = 128; s; s >>= 1) {
        if (threadIdx.x < s) {
            float ov = sv[threadIdx.x + s];
            int   oi = si[threadIdx.x + s];
            if (ov > sv[threadIdx.x] ||
                (ov == sv[threadIdx.x] && oi < si[threadIdx.x])) {
                sv[threadIdx.x] = ov;
                si[threadIdx.x] = oi;
            }
        }
        __syncthreads();
    }
    if (threadIdx.x == 0) out[t] = (float)si[0];
}

// ---------------------------------------------------------------------------
extern "C" void kernel_launch(void* const* d_in, const int* in_sizes, int n_in,
                              void* d_out, int out_size)
{
    const int*   x       = (const int*)  d_in[0];
    const int*   target  = (const int*)  d_in[1];
    const float* eps     = (const float*)d_in[2];
    const float* enc_emb = (const float*)d_in[3];
    const float* enc_Wih = (const float*)d_in[4];
    const float* enc_Whh = (const float*)d_in[5];
    const float* enc_bih = (const float*)d_in[6];
    const float* enc_bhh = (const float*)d_in[7];
    const float* mu_W    = (const float*)d_in[8];
    const float* mu_b    = (const float*)d_in[9];
    const float* lv_W    = (const float*)d_in[10];
    const float* lv_b    = (const float*)d_in[11];
    const float* dec_emb = (const float*)d_in[12];
    const float* dec_Wih = (const float*)d_in[13];
    const float* dec_Whh = (const float*)d_in[14];
    const float* dec_bih = (const float*)d_in[15];
    const float* dec_bhh = (const float*)d_in[16];
    float* out = (float*)d_out;

    cudaFuncSetAttribute(k_main, cudaFuncAttributeMaxDynamicSharedMemorySize,
                         SMEM_BYTES);

    k_pre<<<2048, 256>>>(enc_emb, enc_Wih, enc_bih, enc_bhh,
                         dec_emb, dec_Wih, dec_bih, dec_bhh);
    k_quant<<<2 * G4, 256>>>(enc_Whh, dec_Whh);
    k_main<<<NCTA, 1024, SMEM_BYTES>>>(x, target, eps,
                                       mu_W, mu_b, lv_W, lv_b, out);
    k_argmax<<<512, 256>>>(out);
}

// round 13
// speedup vs baseline: 1.0196x; 1.0196x over previous
#include <cuda_runtime.h>
#include <cuda_bf16.h>

#define H     2048
#define G4    8192          // 4*H gate rows
#define V     28
#define T     512
#define NCTA  148
#define CPB   14            // h-indices per CTA
#define ROWS  56            // gate rows per CTA
#define SMEM_ROWS 49        // rows resident in SMEM; rest (7) stream from L2
#define WMAT  16777216      // G4*H elements per matrix
#define KMAGIC 8421376.0f   // 2^23 + 32768 (biased-u16 float offset)
#define EPOCH 2048u         // stamp-space advance per launch (>= 1026 used)

// dynamic smem layout (u32 units)
#define OFF_W     0
#define OFF_H     (SMEM_ROWS * 1024)            // 50176
#define OFF_PART  (OFF_H + 2048)                // 52224  : 56 rows x 4 slices
#define OFF_C     (OFF_PART + ROWS * 4)         // 52448
#define SMEM_U32  (OFF_C + CPB)                 // 52462
#define SMEM_BYTES (SMEM_U32 * 4)

// ---- device scratch (no allocations allowed) ----
__device__ float          g_table[2u * V * G4]; // [enc/dec][vocab][4H] gate table
__device__ unsigned short g_Wq[2][WMAT];        // biased-u16 quantized Whh
__device__ float          g_wscale[2][G4];      // per-row dequant scales
// hidden state, 4-deep ring, SELF-FLAGGED: low32 = value bits, high32 = stamp.
// Published ONLY via st.release.gpu.b64; polled ONLY via ld.acquire.gpu.b64
// (morally strong ops: single-copy atomic + ordering guaranteed by the model).
__device__ __align__(16) unsigned long long g_hd[4][H];
__device__ unsigned       g_base;               // stamp epoch (+=EPOCH per launch)

__device__ __forceinline__ float warpsum(float v) {
#pragma unroll
    for (int o = 16; o; o >>= 1) v += __shfl_xor_sync(0xffffffffu, v, o);
    return v;
}
__device__ __forceinline__ float sigm(float x) { return 1.0f / (1.0f + expf(-x)); }

// Publish one (value,stamp) word: strong release store (orders all prior
// writes of this thread and, via the preceding __syncthreads, of the CTA).
__device__ __forceinline__ void publish_h(unsigned long long* dst, float v,
                                          unsigned stamp) {
    unsigned long long pk =
        ((unsigned long long)stamp << 32) | (unsigned long long)__float_as_uint(v);
    asm volatile("st.release.gpu.global.b64 [%0], %1;"
                 :: "l"(dst), "l"(pk) : "memory");
}

// Poll two (value,stamp) words with strong acquire loads until the stamps
// match EXACTLY. Per the ring proof stamps never exceed want; if that proof
// is wrong this deadlocks (loud diagnostic) instead of corrupting silently.
__device__ __forceinline__ float2 poll_h2(const unsigned long long* src,
                                          unsigned want) {
    unsigned long long v0, v1;
    do {
        asm volatile("ld.acquire.gpu.global.b64 %0, [%1];"
                     : "=l"(v0) : "l"(src) : "memory");
    } while ((unsigned)(v0 >> 32) != want);
    do {
        asm volatile("ld.acquire.gpu.global.b64 %0, [%1];"
                     : "=l"(v1) : "l"(src + 1) : "memory");
    } while ((unsigned)(v1 >> 32) != want);
    return make_float2(__uint_as_float((unsigned)v0),
                       __uint_as_float((unsigned)v1));
}

// biased-u16 pair -> 2 fp32 (value = 2^23 + biased) via PRMT; no I2F.
#define CVT_LO(u) __uint_as_float(__byte_perm((u), 0x4B000000u, 0x7410))
#define CVT_HI(u) __uint_as_float(__byte_perm((u), 0x4B000000u, 0x7432))

// ---------------------------------------------------------------------------
// Quantize Whh rows to biased uint16 with per-row fp32 scale.
// ---------------------------------------------------------------------------
__global__ __launch_bounds__(256) void k_quant(
    const float* __restrict__ encW, const float* __restrict__ decW)
{
    __shared__ float s_max[8];
    const int r     = blockIdx.x;       // 0..16383
    const int which = r >> 13;
    const int row   = r & (G4 - 1);
    const int tid = threadIdx.x, lane = tid & 31, w = tid >> 5;

    const float4* W4 = reinterpret_cast<const float4*>(
        (which ? decW : encW) + (size_t)row * H);

    float4 v0 = __ldg(&W4[tid]);
    float4 v1 = __ldg(&W4[tid + 256]);

    float m = fmaxf(fmaxf(fabsf(v0.x), fabsf(v0.y)), fmaxf(fabsf(v0.z), fabsf(v0.w)));
    m = fmaxf(m, fmaxf(fmaxf(fabsf(v1.x), fabsf(v1.y)), fmaxf(fabsf(v1.z), fabsf(v1.w))));
#pragma unroll
    for (int o = 16; o; o >>= 1) m = fmaxf(m, __shfl_xor_sync(0xffffffffu, m, o));
    if (lane == 0) s_max[w] = m;
    __syncthreads();
    if (tid == 0) {
        float mm = s_max[0];
#pragma unroll
        for (int i = 1; i < 8; i++) mm = fmaxf(mm, s_max[i]);
        s_max[0] = mm;
        g_wscale[which][row] = mm * (1.0f / 32766.0f);
    }
    __syncthreads();
    const float mv  = s_max[0];
    const float inv = (mv > 0.0f) ? (32766.0f / mv) : 0.0f;

    ushort4* Q4 = reinterpret_cast<ushort4*>(&g_Wq[which][(size_t)row * H]);
    ushort4 q;
    q.x = (unsigned short)(__float2int_rn(v0.x * inv) + 32768);
    q.y = (unsigned short)(__float2int_rn(v0.y * inv) + 32768);
    q.z = (unsigned short)(__float2int_rn(v0.z * inv) + 32768);
    q.w = (unsigned short)(__float2int_rn(v0.w * inv) + 32768);
    Q4[tid] = q;
    q.x = (unsigned short)(__float2int_rn(v1.x * inv) + 32768);
    q.y = (unsigned short)(__float2int_rn(v1.y * inv) + 32768);
    q.z = (unsigned short)(__float2int_rn(v1.z * inv) + 32768);
    q.w = (unsigned short)(__float2int_rn(v1.w * inv) + 32768);
    Q4[tid + 256] = q;
}

// ---------------------------------------------------------------------------
// Precompute per-vocab gate tables; block 0 also advances the stamp epoch and
// publishes S(0)=0 into ring buffer 0 with the new base (graph-replay safe).
// ---------------------------------------------------------------------------
__global__ __launch_bounds__(256) void k_pre(
    const float* __restrict__ enc_emb, const float* __restrict__ enc_Wih,
    const float* __restrict__ enc_bih, const float* __restrict__ enc_bhh,
    const float* __restrict__ dec_emb, const float* __restrict__ dec_Wih,
    const float* __restrict__ dec_bih, const float* __restrict__ dec_bhh)
{
    __shared__ __align__(16) float s_emb[V][256];
    __shared__ unsigned s_base;
    const int tid = threadIdx.x, lane = tid & 31, warp = tid >> 5;

    if (blockIdx.x == 0) {
        if (tid == 0) {
            unsigned nb = g_base + EPOCH;
            g_base = nb;
            s_base = nb;
        }
        __syncthreads();
        const unsigned nb = s_base;
        for (int j = tid; j < H; j += 256)
            publish_h(&g_hd[0][j], 0.0f, nb);
    }

    const int   which = (blockIdx.x >= 1024) ? 1 : 0;
    const float* emb = which ? dec_emb : enc_emb;
    const float* Wih = which ? dec_Wih : enc_Wih;
    const float* bih = which ? dec_bih : enc_bih;
    const float* bhh = which ? dec_bhh : enc_bhh;
    const int row = (blockIdx.x & 1023) * 8 + warp;   // 0..8191

    float acc[V];
#pragma unroll
    for (int v = 0; v < V; v++) acc[v] = 0.0f;

    for (int kt = 0; kt < 8; kt++) {
        const int k0 = kt * 256;
        __syncthreads();
        for (int idx = tid; idx < V * 256; idx += 256) {
            int v = idx >> 8, kk = idx & 255;
            s_emb[v][kk] = __ldg(&emb[v * H + k0 + kk]);
        }
        __syncthreads();
        const float4* Wr = reinterpret_cast<const float4*>(Wih + (size_t)row * H + k0);
#pragma unroll
        for (int it = 0; it < 2; it++) {
            const int kl = it * 32 + lane;
            float4 w4 = __ldg(&Wr[kl]);
#pragma unroll
            for (int v = 0; v < V; v++) {
                float4 e = reinterpret_cast<const float4*>(s_emb[v])[kl];
                acc[v] += w4.x * e.x + w4.y * e.y + w4.z * e.z + w4.w * e.w;
            }
        }
    }

    float bias = 0.0f;
#pragma unroll
    for (int v = 0; v < V; v++) {
        float s = warpsum(acc[v]);
        if (lane == 0) {
            if (v == 0) bias = __ldg(&bih[row]) + __ldg(&bhh[row]);
            g_table[(size_t)which * V * G4 + (size_t)v * G4 + row] = s + bias;
        }
    }
}

// ---------------------------------------------------------------------------
// Persistent LSTM kernel. 148 CTAs x 1024 threads. NO grid barrier: hidden
// state is self-flagged (value+stamp in ONE 64-bit word), published with
// st.release.gpu and polled with ld.acquire.gpu (morally strong). Ring of 4.
// Global step s (0..1024): read S(s) = buf s&3 stamp base+s,
//                          write S(s+1) -> buf (s+1)&3 stamp base+s+1.
//   enc t: s=t        heads: s=512        dec t: s=513+t
// ---------------------------------------------------------------------------
__global__ __launch_bounds__(1024, 1) void k_main(
    const int*   __restrict__ x,      const int*   __restrict__ target,
    const float* __restrict__ eps,
    const float* __restrict__ mu_W,    const float* __restrict__ mu_b,
    const float* __restrict__ lv_W,    const float* __restrict__ lv_b,
    float* __restrict__ out)
{
    extern __shared__ __align__(16) unsigned s_dyn[];
    unsigned* s_w     = s_dyn + OFF_W;               // [49][1024] u32 (2 u16)
    float*    s_h     = (float*)(s_dyn + OFF_H);     // [2048]
    float*    s_part  = (float*)(s_dyn + OFF_PART);  // [56][4]
    float*    s_c     = (float*)(s_dyn + OFF_C);     // [14]

    const int tid = threadIdx.x, lane = tid & 31, w = tid >> 5;
    const int g = w >> 2;        // row-group 0..7
    const int q = w & 3;         // k-slice 0..3
    const int j0 = blockIdx.x * CPB;
    int nloc = H - j0;
    if (nloc > CPB) nloc = CPB;
    if (nloc < 0)  nloc = 0;
    const int nrows = nloc * 4;

    if (tid < CPB) s_c[tid] = 0.0f;

    const unsigned base = g_base;   // set by k_pre this launch

    for (int phase = 0; phase < 2; phase++) {
        const unsigned short* Wq = g_Wq[phase];
        const float* wsc   = g_wscale[phase];
        const float* table = g_table + (size_t)phase * V * G4;

        // ---- load the 49 SMEM-resident weight rows for this phase ----
        __syncthreads();
        {
            const unsigned* Wq32 = reinterpret_cast<const unsigned*>(Wq);
            for (int sidx = 0; sidx < 49; sidx++) {
                int lr = (sidx < 48) ? ((sidx / 6) + 8 * (sidx % 6)) : 48;
                if (lr < nrows) {
                    const int row = (lr & 3) * H + j0 + (lr >> 2);
                    s_w[sidx * 1024 + tid] = __ldg(&Wq32[(size_t)row * 1024 + tid]);
                }
            }
        }
        __syncthreads();

        for (int t = 0; t < T; t++) {
            const int sread = (phase == 0) ? t : (513 + t);
            const int rbuf  = sread & 3;
            const int wbuf  = (sread + 1) & 3;
            const unsigned want = base + (unsigned)sread;

            // prefetch streamed row (one per group, g>=1)
            const int lrs = 48 + g;
            const bool do_stream = (g >= 1) && (lrs < nrows);
            uint2 pf[4];
            if (do_stream) {
                const int row = (lrs & 3) * H + j0 + (lrs >> 2);
                const uint2* gw = reinterpret_cast<const uint2*>(
                    Wq + (size_t)row * H) + q * 128 + lane;
#pragma unroll
                for (int c = 0; c < 4; c++) pf[c] = __ldg(&gw[c * 32]);
            }

            // self-flagged h: poll this thread's two elements, drop into smem
            reinterpret_cast<float2*>(s_h)[tid] =
                poll_h2(&g_hd[rbuf][2 * tid], want);
            __syncthreads();

            // per-warp h-slice in registers: k = q*512 + c*128 + lane*4
            const float4* sh4 = reinterpret_cast<const float4*>(s_h);
            float4 hv[4];
            float hsum = 0.0f;
#pragma unroll
            for (int c = 0; c < 4; c++) {
                hv[c] = sh4[q * 128 + c * 32 + lane];
                hsum += (hv[c].x + hv[c].y) + (hv[c].z + hv[c].w);
            }

            // SMEM rows: k = 0..5 (all g), plus k=6 for g==0
            const int kmax = (g == 0) ? 7 : 6;
#pragma unroll
            for (int k = 0; k < 7; k++) {
                if (k >= kmax) break;
                const int lr = g + 8 * k;
                if (lr < nrows) {
                    const int sidx = (k < 6) ? (g * 6 + k) : 48;
                    const uint2* wp = reinterpret_cast<const uint2*>(s_w) +
                                      (size_t)sidx * 512 + q * 128 + lane;
                    float acc = 0.0f;
#pragma unroll
                    for (int c = 0; c < 4; c++) {
                        uint2 ab = wp[c * 32];
                        acc = fmaf(CVT_LO(ab.x), hv[c].x, acc);
                        acc = fmaf(CVT_HI(ab.x), hv[c].y, acc);
                        acc = fmaf(CVT_LO(ab.y), hv[c].z, acc);
                        acc = fmaf(CVT_HI(ab.y), hv[c].w, acc);
                    }
                    acc = fmaf(-KMAGIC, hsum, acc);   // remove bias term
                    acc = warpsum(acc);
                    if (lane == 0) s_part[lr * 4 + q] = acc;
                }
            }
            if (do_stream) {
                float acc = 0.0f;
#pragma unroll
                for (int c = 0; c < 4; c++) {
                    acc = fmaf(CVT_LO(pf[c].x), hv[c].x, acc);
                    acc = fmaf(CVT_HI(pf[c].x), hv[c].y, acc);
                    acc = fmaf(CVT_LO(pf[c].y), hv[c].z, acc);
                    acc = fmaf(CVT_HI(pf[c].y), hv[c].w, acc);
                }
                acc = fmaf(-KMAGIC, hsum, acc);
                acc = warpsum(acc);
                if (lane == 0) s_part[lrs * 4 + q] = acc;
            }
            __syncthreads();

            // fused combine + dequant + table + cell update (owner threads).
            // The release-stamped store is both publish and sync.
            if (tid < nloc) {
                const int tok = (phase == 0) ? __ldg(&x[t])
                                             : (t == 0 ? 0 : __ldg(&target[t - 1]));
                float gate[4];
#pragma unroll
                for (int ga = 0; ga < 4; ga++) {
                    const int lr = tid * 4 + ga;
                    const int row = ga * H + j0 + tid;
                    float s = (s_part[lr * 4 + 0] + s_part[lr * 4 + 1]) +
                              (s_part[lr * 4 + 2] + s_part[lr * 4 + 3]);
                    gate[ga] = s * __ldg(&wsc[row]) +
                               __ldg(&table[(size_t)tok * G4 + row]);
                }
                float c = sigm(gate[1]) * s_c[tid] + sigm(gate[0]) * tanhf(gate[2]);
                s_c[tid] = c;
                float h = sigm(gate[3]) * tanhf(c);
                publish_h(&g_hd[wbuf][j0 + tid], h, want + 1u);
                if (phase)
                    out[512 + (size_t)t * H + j0 + tid] = h;
            }
            // no grid barrier
        }

        if (phase == 0) {
            // VAE heads: s=512. read h_enc (buf 0, stamp base+512),
            // write z -> buf 1, stamp base+513.
            const unsigned want = base + 512u;
            reinterpret_cast<float2*>(s_h)[tid] =
                poll_h2(&g_hd[0][2 * tid], want);
            __syncthreads();
            const float4* sh4 = reinterpret_cast<const float4*>(s_h);
            if (w < nloc * 2) {
                const int l = w >> 1, m = w & 1;
                const float* Wm = m ? lv_W : mu_W;
                const int row = j0 + l;
                const float4* W4 = reinterpret_cast<const float4*>(Wm) +
                                   (size_t)row * (H / 4);
                float s = 0.0f;
#pragma unroll 8
                for (int i = lane; i < H / 4; i += 32) {
                    float4 a = __ldg(&W4[i]);
                    float4 b = sh4[i];
                    s += a.x * b.x + a.y * b.y + a.z * b.z + a.w * b.w;
                }
                s = warpsum(s);
                if (lane == 0)
                    s_part[w] = s + __ldg(&(m ? lv_b : mu_b)[row]);
            }
            __syncthreads();
            if (tid < nloc) {
                const int j = j0 + tid;
                const float mu = s_part[tid * 2 + 0];
                const float lv = s_part[tid * 2 + 1];
                out[512 + (size_t)T * H + j]     = mu;
                out[512 + (size_t)T * H + H + j] = lv;
                float z = mu + __ldg(&eps[j]) * expf(0.5f * lv);
                publish_h(&g_hd[1][j], z, want + 1u);
            }
        }
    }
}

// ---------------------------------------------------------------------------
// Argmax over hidden dim of each decoder output row (first-index tie-break).
// ---------------------------------------------------------------------------
__global__ __launch_bounds__(256) void k_argmax(float* __restrict__ out)
{
    __shared__ float sv[256];
    __shared__ int   si[256];
    const int t = blockIdx.x;
    const float* row = out + 512 + (size_t)t * H;
    float best = -3.402823466e+38f;
    int   bi = 0;
    for (int j = threadIdx.x; j < H; j += 256) {
        float v = row[j];
        if (v > best) { best = v; bi = j; }
    }
    sv[threadIdx.x] = best;
    si[threadIdx.x] = bi;
    __syncthreads();
    for (int s = 128; s; s >>= 1) {
        if (threadIdx.x < s) {
            float ov = sv[threadIdx.x + s];
            int   oi = si[threadIdx.x + s];
            if (ov > sv[threadIdx.x] ||
                (ov == sv[threadIdx.x] && oi < si[threadIdx.x])) {
                sv[threadIdx.x] = ov;
                si[threadIdx.x] = oi;
            }
        }
        __syncthreads();
    }
    if (threadIdx.x == 0) out[t] = (float)si[0];
}

// ---------------------------------------------------------------------------
extern "C" void kernel_launch(void* const* d_in, const int* in_sizes, int n_in,
                              void* d_out, int out_size)
{
    const int*   x       = (const int*)  d_in[0];
    const int*   target  = (const int*)  d_in[1];
    const float* eps     = (const float*)d_in[2];
    const float* enc_emb = (const float*)d_in[3];
    const float* enc_Wih = (const float*)d_in[4];
    const float* enc_Whh = (const float*)d_in[5];
    const float* enc_bih = (const float*)d_in[6];
    const float* enc_bhh = (const float*)d_in[7];
    const float* mu_W    = (const float*)d_in[8];
    const float* mu_b    = (const float*)d_in[9];
    const float* lv_W    = (const float*)d_in[10];
    const float* lv_b    = (const float*)d_in[11];
    const float* dec_emb = (const float*)d_in[12];
    const float* dec_Wih = (const float*)d_in[13];
    const float* dec_Whh = (const float*)d_in[14];
    const float* dec_bih = (const float*)d_in[15];
    const float* dec_bhh = (const float*)d_in[16];
    float* out = (float*)d_out;

    cudaFuncSetAttribute(k_main, cudaFuncAttributeMaxDynamicSharedMemorySize,
                         SMEM_BYTES);

    k_pre<<<2048, 256>>>(enc_emb, enc_Wih, enc_bih, enc_bhh,
                         dec_emb, dec_Wih, dec_bih, dec_bhh);
    k_quant<<<2 * G4, 256>>>(enc_Whh, dec_Whh);
    k_main<<<NCTA, 1024, SMEM_BYTES>>>(x, target, eps,
                                       mu_W, mu_b, lv_W, lv_b, out);
    k_argmax<<<512, 256>>>(out);
}

// round 14
// speedup vs baseline: 1.0994x; 1.0783x over previous
#include <cuda_runtime.h>
#include <cuda_bf16.h>

#define H     2048
#define G4    8192          // 4*H gate rows
#define V     28
#define T     512
#define NCTA  148
#define CPB   14            // h-indices per CTA
#define ROWS  56            // gate rows per CTA
#define SMEM_ROWS 49        // rows resident in SMEM; rest (7) stream from L2
#define WMAT  16777216      // G4*H elements per matrix
#define KMAGIC 8421376.0f   // 2^23 + 32768 (biased-u16 float offset)
#define EPOCH 2048u         // stamp-space advance per launch (>= 1026 used)

// dynamic smem layout (u32 units)
#define OFF_W     0
#define OFF_H     (SMEM_ROWS * 1024)            // 50176
#define OFF_PART  (OFF_H + 2048)                // 52224  : 56 rows x 4 slices
#define SMEM_U32  (OFF_PART + ROWS * 4)         // 52448
#define SMEM_BYTES (SMEM_U32 * 4)

// ---- device scratch (no allocations allowed) ----
__device__ float          g_table[2u * V * G4]; // [enc/dec][vocab][4H] gate table
__device__ unsigned short g_Wq[2][WMAT];        // biased-u16 quantized Whh
__device__ float          g_wscale[2][G4];      // per-row dequant scales
// hidden state, 4-deep ring, SELF-FLAGGED: low32 = value bits, high32 = stamp.
__device__ __align__(16) unsigned long long g_hd[4][H];
__device__ unsigned       g_base;               // stamp epoch (+=EPOCH per launch)

__device__ __forceinline__ float warpsum(float v) {
#pragma unroll
    for (int o = 16; o; o >>= 1) v += __shfl_xor_sync(0xffffffffu, v, o);
    return v;
}
__device__ __forceinline__ float sigm(float x) { return 1.0f / (1.0f + expf(-x)); }

// Publish one (value,stamp) word: strong release store.
__device__ __forceinline__ void publish_h(unsigned long long* dst, float v,
                                          unsigned stamp) {
    unsigned long long pk =
        ((unsigned long long)stamp << 32) | (unsigned long long)__float_as_uint(v);
    asm volatile("st.release.gpu.global.b64 [%0], %1;"
                 :: "l"(dst), "l"(pk) : "memory");
}

// Poll: cheap weak spin on the stamp words, then one-shot strong acquire
// finals (single-copy-atomic value+stamp, ordered). Exact-match semantics
// preserved from round 13 (proven correct).
__device__ __forceinline__ float2 poll_h2(const unsigned long long* src,
                                          unsigned want) {
    const unsigned* st = reinterpret_cast<const unsigned*>(src);
    unsigned s0, s1;
    do {
        asm volatile("ld.global.cg.u32 %0, [%1];" : "=r"(s0) : "l"(st + 1));
        asm volatile("ld.global.cg.u32 %0, [%1];" : "=r"(s1) : "l"(st + 3));
    } while (s0 != want || s1 != want);
    unsigned long long v0, v1;
    do {
        asm volatile("ld.acquire.gpu.global.b64 %0, [%1];"
                     : "=l"(v0) : "l"(src) : "memory");
    } while ((unsigned)(v0 >> 32) != want);
    do {
        asm volatile("ld.acquire.gpu.global.b64 %0, [%1];"
                     : "=l"(v1) : "l"(src + 1) : "memory");
    } while ((unsigned)(v1 >> 32) != want);
    return make_float2(__uint_as_float((unsigned)v0),
                       __uint_as_float((unsigned)v1));
}

// biased-u16 pair -> 2 fp32 (value = 2^23 + biased) via PRMT; no I2F.
#define CVT_LO(u) __uint_as_float(__byte_perm((u), 0x4B000000u, 0x7410))
#define CVT_HI(u) __uint_as_float(__byte_perm((u), 0x4B000000u, 0x7432))

// 16 FMAs of one row chunk (4x uint2 against hv[0..3]) with dual acc chains.
#define ROW_DOT(w0, w1, w2, w3, OUTVAR)                                   \
    float OUTVAR;                                                         \
    {                                                                     \
        float a0 = 0.0f, a1 = 0.0f;                                       \
        a0 = fmaf(CVT_LO(w0.x), hv[0].x, a0);                             \
        a0 = fmaf(CVT_HI(w0.x), hv[0].y, a0);                             \
        a0 = fmaf(CVT_LO(w0.y), hv[0].z, a0);                             \
        a0 = fmaf(CVT_HI(w0.y), hv[0].w, a0);                             \
        a1 = fmaf(CVT_LO(w1.x), hv[1].x, a1);                             \
        a1 = fmaf(CVT_HI(w1.x), hv[1].y, a1);                             \
        a1 = fmaf(CVT_LO(w1.y), hv[1].z, a1);                             \
        a1 = fmaf(CVT_HI(w1.y), hv[1].w, a1);                             \
        a0 = fmaf(CVT_LO(w2.x), hv[2].x, a0);                             \
        a0 = fmaf(CVT_HI(w2.x), hv[2].y, a0);                             \
        a0 = fmaf(CVT_LO(w2.y), hv[2].z, a0);                             \
        a0 = fmaf(CVT_HI(w2.y), hv[2].w, a0);                             \
        a1 = fmaf(CVT_LO(w3.x), hv[3].x, a1);                             \
        a1 = fmaf(CVT_HI(w3.x), hv[3].y, a1);                             \
        a1 = fmaf(CVT_LO(w3.y), hv[3].z, a1);                             \
        a1 = fmaf(CVT_HI(w3.y), hv[3].w, a1);                             \
        OUTVAR = fmaf(-KMAGIC, hsum, a0 + a1);                            \
    }

// ---------------------------------------------------------------------------
// Quantize Whh rows to biased uint16 with per-row fp32 scale.
// ---------------------------------------------------------------------------
__global__ __launch_bounds__(256) void k_quant(
    const float* __restrict__ encW, const float* __restrict__ decW)
{
    __shared__ float s_max[8];
    const int r     = blockIdx.x;       // 0..16383
    const int which = r >> 13;
    const int row   = r & (G4 - 1);
    const int tid = threadIdx.x, lane = tid & 31, w = tid >> 5;

    const float4* W4 = reinterpret_cast<const float4*>(
        (which ? decW : encW) + (size_t)row * H);

    float4 v0 = __ldg(&W4[tid]);
    float4 v1 = __ldg(&W4[tid + 256]);

    float m = fmaxf(fmaxf(fabsf(v0.x), fabsf(v0.y)), fmaxf(fabsf(v0.z), fabsf(v0.w)));
    m = fmaxf(m, fmaxf(fmaxf(fabsf(v1.x), fabsf(v1.y)), fmaxf(fabsf(v1.z), fabsf(v1.w))));
#pragma unroll
    for (int o = 16; o; o >>= 1) m = fmaxf(m, __shfl_xor_sync(0xffffffffu, m, o));
    if (lane == 0) s_max[w] = m;
    __syncthreads();
    if (tid == 0) {
        float mm = s_max[0];
#pragma unroll
        for (int i = 1; i < 8; i++) mm = fmaxf(mm, s_max[i]);
        s_max[0] = mm;
        g_wscale[which][row] = mm * (1.0f / 32766.0f);
    }
    __syncthreads();
    const float mv  = s_max[0];
    const float inv = (mv > 0.0f) ? (32766.0f / mv) : 0.0f;

    ushort4* Q4 = reinterpret_cast<ushort4*>(&g_Wq[which][(size_t)row * H]);
    ushort4 q;
    q.x = (unsigned short)(__float2int_rn(v0.x * inv) + 32768);
    q.y = (unsigned short)(__float2int_rn(v0.y * inv) + 32768);
    q.z = (unsigned short)(__float2int_rn(v0.z * inv) + 32768);
    q.w = (unsigned short)(__float2int_rn(v0.w * inv) + 32768);
    Q4[tid] = q;
    q.x = (unsigned short)(__float2int_rn(v1.x * inv) + 32768);
    q.y = (unsigned short)(__float2int_rn(v1.y * inv) + 32768);
    q.z = (unsigned short)(__float2int_rn(v1.z * inv) + 32768);
    q.w = (unsigned short)(__float2int_rn(v1.w * inv) + 32768);
    Q4[tid + 256] = q;
}

// ---------------------------------------------------------------------------
// Precompute per-vocab gate tables; block 0 also advances the stamp epoch and
// publishes S(0)=0 into ring buffer 0 with the new base (graph-replay safe).
// ---------------------------------------------------------------------------
__global__ __launch_bounds__(256) void k_pre(
    const float* __restrict__ enc_emb, const float* __restrict__ enc_Wih,
    const float* __restrict__ enc_bih, const float* __restrict__ enc_bhh,
    const float* __restrict__ dec_emb, const float* __restrict__ dec_Wih,
    const float* __restrict__ dec_bih, const float* __restrict__ dec_bhh)
{
    __shared__ __align__(16) float s_emb[V][256];
    __shared__ unsigned s_base;
    const int tid = threadIdx.x, lane = tid & 31, warp = tid >> 5;

    if (blockIdx.x == 0) {
        if (tid == 0) {
            unsigned nb = g_base + EPOCH;
            g_base = nb;
            s_base = nb;
        }
        __syncthreads();
        const unsigned nb = s_base;
        for (int j = tid; j < H; j += 256)
            publish_h(&g_hd[0][j], 0.0f, nb);
    }

    const int   which = (blockIdx.x >= 1024) ? 1 : 0;
    const float* emb = which ? dec_emb : enc_emb;
    const float* Wih = which ? dec_Wih : enc_Wih;
    const float* bih = which ? dec_bih : enc_bih;
    const float* bhh = which ? dec_bhh : enc_bhh;
    const int row = (blockIdx.x & 1023) * 8 + warp;   // 0..8191

    float acc[V];
#pragma unroll
    for (int v = 0; v < V; v++) acc[v] = 0.0f;

    for (int kt = 0; kt < 8; kt++) {
        const int k0 = kt * 256;
        __syncthreads();
        for (int idx = tid; idx < V * 256; idx += 256) {
            int v = idx >> 8, kk = idx & 255;
            s_emb[v][kk] = __ldg(&emb[v * H + k0 + kk]);
        }
        __syncthreads();
        const float4* Wr = reinterpret_cast<const float4*>(Wih + (size_t)row * H + k0);
#pragma unroll
        for (int it = 0; it < 2; it++) {
            const int kl = it * 32 + lane;
            float4 w4 = __ldg(&Wr[kl]);
#pragma unroll
            for (int v = 0; v < V; v++) {
                float4 e = reinterpret_cast<const float4*>(s_emb[v])[kl];
                acc[v] += w4.x * e.x + w4.y * e.y + w4.z * e.z + w4.w * e.w;
            }
        }
    }

    float bias = 0.0f;
#pragma unroll
    for (int v = 0; v < V; v++) {
        float s = warpsum(acc[v]);
        if (lane == 0) {
            if (v == 0) bias = __ldg(&bih[row]) + __ldg(&bhh[row]);
            g_table[(size_t)which * V * G4 + (size_t)v * G4 + row] = s + bias;
        }
    }
}

// ---------------------------------------------------------------------------
// Persistent LSTM kernel. 148 CTAs x 1024 threads. Sync identical to R13
// (self-flagged h, acquire/release). Compute restructured for ILP:
// full CTAs take an unrolled fast path; owner chain latency-hidden via
// prefetch (tok pre-poll, table post-stage, wsc per phase, c in register).
// ---------------------------------------------------------------------------
__global__ __launch_bounds__(1024, 1) void k_main(
    const int*   __restrict__ x,      const int*   __restrict__ target,
    const float* __restrict__ eps,
    const float* __restrict__ mu_W,    const float* __restrict__ mu_b,
    const float* __restrict__ lv_W,    const float* __restrict__ lv_b,
    float* __restrict__ out)
{
    extern __shared__ __align__(16) unsigned s_dyn[];
    unsigned* s_w     = s_dyn + OFF_W;               // [49][1024] u32 (2 u16)
    float*    s_h     = (float*)(s_dyn + OFF_H);     // [2048]
    float*    s_part  = (float*)(s_dyn + OFF_PART);  // [56][4]

    const int tid = threadIdx.x, lane = tid & 31, w = tid >> 5;
    const int g = w >> 2;        // row-group 0..7
    const int q = w & 3;         // k-slice 0..3
    const int j0 = blockIdx.x * CPB;
    int nloc = H - j0;
    if (nloc > CPB) nloc = CPB;
    if (nloc < 0)  nloc = 0;
    const int nrows = nloc * 4;
    const bool full = (nloc == CPB);

    float cacc = 0.0f;                       // LSTM cell state (owner threads)
    const unsigned base = g_base;            // set by k_pre this launch

    for (int phase = 0; phase < 2; phase++) {
        const unsigned short* Wq = g_Wq[phase];
        const float* wsc   = g_wscale[phase];
        const float* table = g_table + (size_t)phase * V * G4;

        // ---- load the 49 SMEM-resident weight rows for this phase ----
        __syncthreads();
        {
            const unsigned* Wq32 = reinterpret_cast<const unsigned*>(Wq);
            for (int sidx = 0; sidx < 49; sidx++) {
                int lr = (sidx < 48) ? ((sidx / 6) + 8 * (sidx % 6)) : 48;
                if (lr < nrows) {
                    const int row = (lr & 3) * H + j0 + (lr >> 2);
                    s_w[sidx * 1024 + tid] = __ldg(&Wq32[(size_t)row * 1024 + tid]);
                }
            }
        }
        __syncthreads();

        // per-phase register caches
        uint2 pf48[4];                        // g==0: smem row 48 (static)
        if (g == 0) {
            const uint2* wp = reinterpret_cast<const uint2*>(s_w) +
                              (size_t)48 * 512 + q * 128 + lane;
#pragma unroll
            for (int c = 0; c < 4; c++) pf48[c] = wp[c * 32];
        }
        float wscR[4];                        // owner dequant scales (static)
        if (tid < nloc) {
#pragma unroll
            for (int ga = 0; ga < 4; ga++)
                wscR[ga] = __ldg(&wsc[ga * H + j0 + tid]);
        }

        for (int t = 0; t < T; t++) {
            const int sread = (phase == 0) ? t : (513 + t);
            const int rbuf  = sread & 3;
            const int wbuf  = (sread + 1) & 3;
            const unsigned want = base + (unsigned)sread;

            // owner: issue tok load before the poll (hidden by it)
            int tok = 0;
            if (tid < nloc)
                tok = (phase == 0) ? __ldg(&x[t])
                                   : (t == 0 ? 0 : __ldg(&target[t - 1]));

            // stream prefetch (g>=1): this warp's 7th row from L2
            const int lrs = 48 + g;
            const bool strm = (g >= 1) && (lrs < nrows);
            uint2 pfr[4];
            if (strm) {
                const int row = (lrs & 3) * H + j0 + (lrs >> 2);
                const uint2* gw = reinterpret_cast<const uint2*>(
                    Wq + (size_t)row * H) + q * 128 + lane;
#pragma unroll
                for (int c = 0; c < 4; c++) pfr[c] = __ldg(&gw[c * 32]);
            }

            // self-flagged h: poll this thread's two elements, drop into smem
            reinterpret_cast<float2*>(s_h)[tid] =
                poll_h2(&g_hd[rbuf][2 * tid], want);
            __syncthreads();

            // owner: prefetch the 4 table entries (consumed after the dot)
            float tpre[4];
            if (tid < nloc) {
#pragma unroll
                for (int ga = 0; ga < 4; ga++)
                    tpre[ga] = __ldg(&table[(size_t)tok * G4 + ga * H + j0 + tid]);
            }

            // per-warp h-slice in registers: k = q*512 + c*128 + lane*4
            const float4* sh4 = reinterpret_cast<const float4*>(s_h);
            float4 hv[4];
            float hsum = 0.0f;
#pragma unroll
            for (int c = 0; c < 4; c++) {
                hv[c] = sh4[q * 128 + c * 32 + lane];
                hsum += (hv[c].x + hv[c].y) + (hv[c].z + hv[c].w);
            }

            if (full) {
                // ---- fast path: fully unrolled 6 smem rows + row 48+g ----
                const uint2* wbase = reinterpret_cast<const uint2*>(s_w) +
                                     (size_t)(g * 6) * 512 + q * 128 + lane;
#pragma unroll
                for (int k = 0; k < 6; k++) {
                    const uint2* wp = wbase + (size_t)k * 512;
                    uint2 w0 = wp[0], w1 = wp[32], w2 = wp[64], w3 = wp[96];
                    ROW_DOT(w0, w1, w2, w3, accr)
                    float s = warpsum(accr);
                    if (lane == 0) s_part[(g + 8 * k) * 4 + q] = s;
                }
                {
                    uint2 w0, w1, w2, w3;
                    if (g == 0) { w0 = pf48[0]; w1 = pf48[1]; w2 = pf48[2]; w3 = pf48[3]; }
                    else        { w0 = pfr[0];  w1 = pfr[1];  w2 = pfr[2];  w3 = pfr[3]; }
                    ROW_DOT(w0, w1, w2, w3, accr)
                    float s = warpsum(accr);
                    if (lane == 0) s_part[(48 + g) * 4 + q] = s;
                }
            } else if (nloc > 0) {
                // ---- slow path (tail CTAs): guarded loops ----
                const int kmax = (g == 0) ? 7 : 6;
                for (int k = 0; k < kmax; k++) {
                    const int lr = g + 8 * k;
                    if (lr < nrows) {
                        const int sidx = (k < 6) ? (g * 6 + k) : 48;
                        const uint2* wp = reinterpret_cast<const uint2*>(s_w) +
                                          (size_t)sidx * 512 + q * 128 + lane;
                        uint2 w0 = wp[0], w1 = wp[32], w2 = wp[64], w3 = wp[96];
                        ROW_DOT(w0, w1, w2, w3, accr)
                        float s = warpsum(accr);
                        if (lane == 0) s_part[lr * 4 + q] = s;
                    }
                }
                if (strm) {
                    ROW_DOT(pfr[0], pfr[1], pfr[2], pfr[3], accr)
                    float s = warpsum(accr);
                    if (lane == 0) s_part[lrs * 4 + q] = s;
                }
            }
            __syncthreads();

            // fused combine + dequant + table + cell update (owner threads)
            if (tid < nloc) {
                const float4* sp4 = reinterpret_cast<const float4*>(s_part);
                float4 p0 = sp4[tid * 4 + 0];
                float4 p1 = sp4[tid * 4 + 1];
                float4 p2 = sp4[tid * 4 + 2];
                float4 p3 = sp4[tid * 4 + 3];
                float g0 = ((p0.x + p0.y) + (p0.z + p0.w)) * wscR[0] + tpre[0];
                float g1 = ((p1.x + p1.y) + (p1.z + p1.w)) * wscR[1] + tpre[1];
                float g2 = ((p2.x + p2.y) + (p2.z + p2.w)) * wscR[2] + tpre[2];
                float g3 = ((p3.x + p3.y) + (p3.z + p3.w)) * wscR[3] + tpre[3];
                float c = sigm(g1) * cacc + sigm(g0) * tanhf(g2);
                cacc = c;
                float h = sigm(g3) * tanhf(c);
                publish_h(&g_hd[wbuf][j0 + tid], h, want + 1u);
                if (phase)
                    out[512 + (size_t)t * H + j0 + tid] = h;
            }
            // no grid barrier
        }

        if (phase == 0) {
            // VAE heads: s=512. read h_enc (buf 0, stamp base+512),
            // write z -> buf 1, stamp base+513.
            const unsigned want = base + 512u;
            reinterpret_cast<float2*>(s_h)[tid] =
                poll_h2(&g_hd[0][2 * tid], want);
            __syncthreads();
            const float4* sh4 = reinterpret_cast<const float4*>(s_h);
            if (w < nloc * 2) {
                const int l = w >> 1, m = w & 1;
                const float* Wm = m ? lv_W : mu_W;
                const int row = j0 + l;
                const float4* W4 = reinterpret_cast<const float4*>(Wm) +
                                   (size_t)row * (H / 4);
                float s = 0.0f;
#pragma unroll 8
                for (int i = lane; i < H / 4; i += 32) {
                    float4 a = __ldg(&W4[i]);
                    float4 b = sh4[i];
                    s += a.x * b.x + a.y * b.y + a.z * b.z + a.w * b.w;
                }
                s = warpsum(s);
                if (lane == 0)
                    s_part[w] = s + __ldg(&(m ? lv_b : mu_b)[row]);
            }
            __syncthreads();
            if (tid < nloc) {
                const int j = j0 + tid;
                const float mu = s_part[tid * 2 + 0];
                const float lv = s_part[tid * 2 + 1];
                out[512 + (size_t)T * H + j]     = mu;
                out[512 + (size_t)T * H + H + j] = lv;
                float z = mu + __ldg(&eps[j]) * expf(0.5f * lv);
                publish_h(&g_hd[1][j], z, want + 1u);
            }
        }
    }
}

// ---------------------------------------------------------------------------
// Argmax over hidden dim of each decoder output row (first-index tie-break).
// ---------------------------------------------------------------------------
__global__ __launch_bounds__(256) void k_argmax(float* __restrict__ out)
{
    __shared__ float sv[256];
    __shared__ int   si[256];
    const int t = blockIdx.x;
    const float* row = out + 512 + (size_t)t * H;
    float best = -3.402823466e+38f;
    int   bi = 0;
    for (int j = threadIdx.x; j < H; j += 256) {
        float v = row[j];
        if (v > best) { best = v; bi = j; }
    }
    sv[threadIdx.x] = best;
    si[threadIdx.x] = bi;
    __syncthreads();
    for (int s = 128; s; s >>= 1) {
        if (threadIdx.x < s) {
            float ov = sv[threadIdx.x + s];
            int   oi = si[threadIdx.x + s];
            if (ov > sv[threadIdx.x] ||
                (ov == sv[threadIdx.x] && oi < si[threadIdx.x])) {
                sv[threadIdx.x] = ov;
                si[threadIdx.x] = oi;
            }
        }
        __syncthreads();
    }
    if (threadIdx.x == 0) out[t] = (float)si[0];
}

// ---------------------------------------------------------------------------
extern "C" void kernel_launch(void* const* d_in, const int* in_sizes, int n_in,
                              void* d_out, int out_size)
{
    const int*   x       = (const int*)  d_in[0];
    const int*   target  = (const int*)  d_in[1];
    const float* eps     = (const float*)d_in[2];
    const float* enc_emb = (const float*)d_in[3];
    const float* enc_Wih = (const float*)d_in[4];
    const float* enc_Whh = (const float*)d_in[5];
    const float* enc_bih = (const float*)d_in[6];
    const float* enc_bhh = (const float*)d_in[7];
    const float* mu_W    = (const float*)d_in[8];
    const float* mu_b    = (const float*)d_in[9];
    const float* lv_W    = (const float*)d_in[10];
    const float* lv_b    = (const float*)d_in[11];
    const float* dec_emb = (const float*)d_in[12];
    const float* dec_Wih = (const float*)d_in[13];
    const float* dec_Whh = (const float*)d_in[14];
    const float* dec_bih = (const float*)d_in[15];
    const float* dec_bhh = (const float*)d_in[16];
    float* out = (float*)d_out;

    cudaFuncSetAttribute(k_main, cudaFuncAttributeMaxDynamicSharedMemorySize,
                         SMEM_BYTES);

    k_pre<<<2048, 256>>>(enc_emb, enc_Wih, enc_bih, enc_bhh,
                         dec_emb, dec_Wih, dec_bih, dec_bhh);
    k_quant<<<2 * G4, 256>>>(enc_Whh, dec_Whh);
    k_main<<<NCTA, 1024, SMEM_BYTES>>>(x, target, eps,
                                       mu_W, mu_b, lv_W, lv_b, out);
    k_argmax<<<512, 256>>>(out);
}